// round 6
// baseline (speedup 1.0000x reference)
#include <cuda_runtime.h>
#include <cuda_bf16.h>
#include <math_constants.h>
#include <cstdint>

// Problem dims
#define BATCH   256
#define CIN     512
#define KHW     49
#define KD      25088        // 512*49
#define COUT    1000
#define NPAD    1024
#define KSPLIT  16
#define KSEG    (KD / KSPLIT)     // 1568
#define NCHUNK  (KSEG / 16)       // 98

// Scratch (device globals only)
__device__ float g_partial[KSPLIT * BATCH * NPAD];   // 16.8 MB
__device__ int   g_top2[BATCH * 2];
__device__ float g_spd_part[BATCH * 4 * 4];          // [n][ct][4]

// ---------------------------------------------------------------------------
// helpers
// ---------------------------------------------------------------------------
__device__ __forceinline__ void bsplit(float v, __nv_bfloat16& h, __nv_bfloat16& l) {
    h = __float2bfloat16_rn(v);
    l = __float2bfloat16_rn(v - __bfloat162float(h));
}

__device__ __forceinline__ unsigned packbf(__nv_bfloat16 a, __nv_bfloat16 b) {
    unsigned short x = *(unsigned short*)&a;
    unsigned short y = *(unsigned short*)&b;
    return (unsigned)x | ((unsigned)y << 16);
}

__device__ __forceinline__ unsigned smaddr(const void* p) {
    return (unsigned)__cvta_generic_to_shared(p);
}

__device__ __forceinline__ void ldsm4(unsigned r[4], unsigned a) {
    asm volatile("ldmatrix.sync.aligned.m8n8.x4.shared.b16 {%0,%1,%2,%3}, [%4];"
                 : "=r"(r[0]), "=r"(r[1]), "=r"(r[2]), "=r"(r[3]) : "r"(a));
}
__device__ __forceinline__ void ldsm4t(unsigned r[4], unsigned a) {
    asm volatile("ldmatrix.sync.aligned.m8n8.x4.trans.shared.b16 {%0,%1,%2,%3}, [%4];"
                 : "=r"(r[0]), "=r"(r[1]), "=r"(r[2]), "=r"(r[3]) : "r"(a));
}

__device__ __forceinline__ void mma16816(float* d, const unsigned* a, const unsigned* b) {
    asm volatile(
        "mma.sync.aligned.m16n8k16.row.col.f32.bf16.bf16.f32 "
        "{%0,%1,%2,%3}, {%4,%5,%6,%7}, {%8,%9}, {%0,%1,%2,%3};\n"
        : "+f"(d[0]), "+f"(d[1]), "+f"(d[2]), "+f"(d[3])
        : "r"(a[0]), "r"(a[1]), "r"(a[2]), "r"(a[3]), "r"(b[0]), "r"(b[1]));
}

// ---------------------------------------------------------------------------
// Kernel 1: FC GEMM, bf16-split mma, double-buffered smem, ldmatrix frags.
// part[ks][m][n] = sum_k A[m,k]*W[n,k]
// grid (8 ntiles, 2 mtiles, 16 ksplit), 256 thr, tile 128x128, BK=16
// warps 2(m) x 4(n): warp = 64m x 32n
// ---------------------------------------------------------------------------
#define ASTR 24                       // bf16 row stride (48B: LDSM-conflict-free)
#define GTILE (128 * ASTR * 2)        // 6144 B per matrix-part
#define GSET  (4 * GTILE)             // Ah,Al,Wh,Wl per buffer = 24576
#define GEMM_SMEM (2 * GSET)          // 49152

__global__ __launch_bounds__(256) void gemm_mma_kernel(
    const float* __restrict__ A, const float* __restrict__ W)
{
    extern __shared__ char smraw[];

    const int t    = threadIdx.x;
    const int lane = t & 31, wid = t >> 5;
    const int wm = wid >> 2, wn = wid & 3;
    const int g = lane >> 2, tg = lane & 3;
    const int lr  = lane & 7;
    const int lg1 = (lane >> 3) & 1;
    const int lg2 = lane >> 4;

    const int n0 = blockIdx.x * 128;
    const int m0 = blockIdx.y * 128;
    const int k0 = blockIdx.z * KSEG;

    int lrow[2], lkq[2];
    bool wvv[2];
#pragma unroll
    for (int i = 0; i < 2; i++) {
        int idx = t + i * 256;
        lrow[i] = idx >> 2;
        lkq[i]  = idx & 3;
        wvv[i]  = (n0 + lrow[i]) < COUT;
    }

    float acc[4][4][4];
#pragma unroll
    for (int a = 0; a < 4; a++)
#pragma unroll
        for (int b = 0; b < 4; b++)
#pragma unroll
            for (int c = 0; c < 4; c++) acc[a][b][c] = 0.f;

    float4 pa[2], pw[2];

    auto loadchunk = [&](int c) {
        int kb = k0 + c * 16;
#pragma unroll
        for (int i = 0; i < 2; i++) {
            pa[i] = *(const float4*)(A + (size_t)(m0 + lrow[i]) * KD + kb + lkq[i] * 4);
            pw[i] = wvv[i] ? *(const float4*)(W + (size_t)(n0 + lrow[i]) * KD + kb + lkq[i] * 4)
                           : make_float4(0.f, 0.f, 0.f, 0.f);
        }
    };
    auto storechunk = [&](int buf) {
        __nv_bfloat16* dAh = (__nv_bfloat16*)(smraw + buf * GSET + 0 * GTILE);
        __nv_bfloat16* dAl = (__nv_bfloat16*)(smraw + buf * GSET + 1 * GTILE);
        __nv_bfloat16* dWh = (__nv_bfloat16*)(smraw + buf * GSET + 2 * GTILE);
        __nv_bfloat16* dWl = (__nv_bfloat16*)(smraw + buf * GSET + 3 * GTILE);
#pragma unroll
        for (int i = 0; i < 2; i++) {
            const float av[4]  = {pa[i].x, pa[i].y, pa[i].z, pa[i].w};
            const float wv4[4] = {pw[i].x, pw[i].y, pw[i].z, pw[i].w};
            int base = lrow[i] * ASTR + lkq[i] * 4;
            __nv_bfloat16 h[4], l[4];
#pragma unroll
            for (int j = 0; j < 4; j++) bsplit(av[j], h[j], l[j]);
            *(uint2*)&dAh[base] = make_uint2(packbf(h[0], h[1]), packbf(h[2], h[3]));
            *(uint2*)&dAl[base] = make_uint2(packbf(l[0], l[1]), packbf(l[2], l[3]));
#pragma unroll
            for (int j = 0; j < 4; j++) bsplit(wv4[j], h[j], l[j]);
            *(uint2*)&dWh[base] = make_uint2(packbf(h[0], h[1]), packbf(h[2], h[3]));
            *(uint2*)&dWl[base] = make_uint2(packbf(l[0], l[1]), packbf(l[2], l[3]));
        }
    };

    loadchunk(0);
    storechunk(0);
    loadchunk(1);
    __syncthreads();

    // per-thread LDSM base offsets (bytes), relative to each tile base
    const unsigned offA = (unsigned)(((wm * 64 + lr + lg1 * 8) * ASTR + lg2 * 8) * 2);
    const unsigned offB = (unsigned)(((wn * 32 + lr + lg1 * 8) * ASTR + lg2 * 8) * 2);

    for (int c = 0; c < NCHUNK; c++) {
        if (c + 1 < NCHUNK) storechunk((c + 1) & 1);
        if (c + 2 < NCHUNK) loadchunk(c + 2);

        const char* bufp = smraw + (c & 1) * GSET;
        const unsigned aAh = smaddr(bufp + 0 * GTILE) + offA;
        const unsigned aAl = smaddr(bufp + 1 * GTILE) + offA;
        const unsigned aWh = smaddr(bufp + 2 * GTILE) + offB;
        const unsigned aWl = smaddr(bufp + 3 * GTILE) + offB;

        unsigned bh[4][2], bl[4][2], r[4];
#pragma unroll
        for (int p = 0; p < 2; p++) {
            ldsm4(r, aWh + p * 16 * ASTR * 2);
            bh[2*p][0] = r[0]; bh[2*p+1][0] = r[1]; bh[2*p][1] = r[2]; bh[2*p+1][1] = r[3];
            ldsm4(r, aWl + p * 16 * ASTR * 2);
            bl[2*p][0] = r[0]; bl[2*p+1][0] = r[1]; bl[2*p][1] = r[2]; bl[2*p+1][1] = r[3];
        }
#pragma unroll
        for (int mi = 0; mi < 4; mi++) {
            unsigned ah[4], al[4];
            ldsm4(ah, aAh + mi * 16 * ASTR * 2);
            ldsm4(al, aAl + mi * 16 * ASTR * 2);
#pragma unroll
            for (int ni = 0; ni < 4; ni++) {
                mma16816(acc[mi][ni], ah, bh[ni]);
                mma16816(acc[mi][ni], ah, bl[ni]);
                mma16816(acc[mi][ni], al, bh[ni]);
            }
        }
        __syncthreads();
    }

    float* part = g_partial + (size_t)blockIdx.z * BATCH * NPAD;
#pragma unroll
    for (int mi = 0; mi < 4; mi++)
#pragma unroll
        for (int ni = 0; ni < 4; ni++)
#pragma unroll
            for (int v = 0; v < 4; v++) {
                int m = m0 + wm * 64 + mi * 16 + g + ((v >= 2) ? 8 : 0);
                int n = n0 + wn * 32 + ni * 8 + tg * 2 + (v & 1);
                part[(size_t)m * NPAD + n] = acc[mi][ni][v];
            }
}

// ---------------------------------------------------------------------------
// Kernel 2: fused split-K reduce + bias + top-2.  One block per sample m.
// ---------------------------------------------------------------------------
__global__ __launch_bounds__(256) void reduce_top2_kernel(
    const float* __restrict__ bias, float* __restrict__ outR)
{
    const int m = blockIdx.x;
    const int tid = threadIdx.x;

    float v1 = -CUDART_INF_F, v2 = -CUDART_INF_F;
    int   i1 = 0x7fffffff,   i2 = 0x7fffffff;

#pragma unroll
    for (int it = 0; it < 4; it++) {
        int n = tid + it * 256;
        if (n >= COUT) break;
        float s = bias[n];
#pragma unroll
        for (int ks = 0; ks < KSPLIT; ks++)
            s += g_partial[(size_t)ks * BATCH * NPAD + (size_t)m * NPAD + n];
        outR[m * COUT + n] = s;
        if (s > v1 || (s == v1 && n < i1)) { v2 = v1; i2 = i1; v1 = s; i1 = n; }
        else if (s > v2 || (s == v2 && n < i2)) { v2 = s; i2 = n; }
    }

    __shared__ float sv1[256], sv2[256];
    __shared__ int   si1[256], si2[256];
    sv1[tid] = v1; si1[tid] = i1; sv2[tid] = v2; si2[tid] = i2;
    __syncthreads();

    for (int s = 128; s > 0; s >>= 1) {
        if (tid < s) {
            float a1 = sv1[tid],   a2 = sv2[tid];
            int   b1 = si1[tid],   b2 = si2[tid];
            float w1 = sv1[tid+s], w2 = sv2[tid+s];
            int   j1 = si1[tid+s], j2 = si2[tid+s];
            float r1, r2; int q1, q2;
            if (w1 > a1 || (w1 == a1 && j1 < b1)) {
                r1 = w1; q1 = j1;
                if (a1 > w2 || (a1 == w2 && b1 < j2)) { r2 = a1; q2 = b1; }
                else                                   { r2 = w2; q2 = j2; }
            } else {
                r1 = a1; q1 = b1;
                if (w1 > a2 || (w1 == a2 && j1 < b2)) { r2 = w1; q2 = j1; }
                else                                   { r2 = a2; q2 = b2; }
            }
            sv1[tid] = r1; si1[tid] = q1; sv2[tid] = r2; si2[tid] = q2;
        }
        __syncthreads();
    }
    if (tid == 0) {
        g_top2[m * 2 + 0] = si1[0];
        g_top2[m * 2 + 1] = si2[0];
    }
}

// ---------------------------------------------------------------------------
// Kernel 3: SPD path via B = S_n * A_stack  (per-n GEMM), double-buffered.
// A_stack stored d-major in smem: [64 d rows][136 j cols] per chunk, loaded
// into B-frags via ldmatrix.trans.  j in [0,49) -> w0 ; [64,113) -> w1.
// B[c,j] = sum_d S[n][c][d] * A_stack[d,j]   (M=128 c-tile, N=128, K=512)
// out[k,m] = sum_{c,hw} A_m[c,hw] * B[c, j(k,hw)]
// grid (4 c-tiles, 256 n), 256 thr, warps 2(c) x 4(j).
// ---------------------------------------------------------------------------
#define SSTR 72
#define STILE (128 * SSTR * 2)        // 18432 B per S part
#define JSTR  136
#define WTILE (64 * JSTR * 2)         // 17408 B per A_stack part
#define OFF_W (4 * STILE)             // 73728
#define SPD_SMEM (OFF_W + 4 * WTILE)  // 143360
#define AFSTR 100

__global__ __launch_bounds__(256) void spd_mma_kernel(
    const float* __restrict__ SPD, const float* __restrict__ W)
{
    extern __shared__ char sm[];

    const int t = threadIdx.x;
    const int lane = t & 31, wid = t >> 5;
    const int wr = wid >> 2, ws = wid & 3;
    const int g = lane >> 2, tg = lane & 3;
    const int lr  = lane & 7;
    const int lg1 = (lane >> 3) & 1;
    const int lg2 = lane >> 4;

    const int n  = blockIdx.y;
    const int c0 = blockIdx.x * 128;

    const int o0 = g_top2[n * 2 + 0];
    const int o1 = g_top2[n * 2 + 1];
    const float* w0 = W + (size_t)o0 * KD;
    const float* w1 = W + (size_t)o1 * KD;
    const float* Sn = SPD + (size_t)n * CIN * CIN;

    // zero-pad j cols 49..63 and 113..127 of both A_stack buffers (h & l)
    for (int idx = t; idx < 64 * 30; idx += 256) {
        int r = idx / 30;
        int q = idx - r * 30;
        int col = (q < 15) ? (49 + q) : (113 + q - 15);
#pragma unroll
        for (int b = 0; b < 4; b++) {
            __nv_bfloat16* Wb = (__nv_bfloat16*)(sm + OFF_W + b * WTILE);
            Wb[r * JSTR + col] = __float2bfloat16(0.f);
        }
    }

    float acc[4][4][4];
#pragma unroll
    for (int a = 0; a < 4; a++)
#pragma unroll
        for (int b = 0; b < 4; b++)
#pragma unroll
            for (int c = 0; c < 4; c++) acc[a][b][c] = 0.f;

    float4 ps[8];
    float  pw0[13], pw1[13];

    auto loadchunk = [&](int ch) {
        int dch = ch * 64;
#pragma unroll
        for (int i = 0; i < 8; i++) {
            int idx = t + i * 256;
            int c = idx >> 4, q = idx & 15;
            ps[i] = *(const float4*)(Sn + (size_t)(c0 + c) * CIN + dch + q * 4);
        }
#pragma unroll
        for (int i = 0; i < 13; i++) {
            int idx = t + i * 256;
            if (idx < 3136) {
                pw0[i] = w0[dch * KHW + idx];
                pw1[i] = w1[dch * KHW + idx];
            }
        }
    };
    auto storechunk = [&](int buf) {
        __nv_bfloat16* Sh = (__nv_bfloat16*)(sm + buf * 2 * STILE);
        __nv_bfloat16* Sl = (__nv_bfloat16*)(sm + buf * 2 * STILE + STILE);
        __nv_bfloat16* Wh = (__nv_bfloat16*)(sm + OFF_W + buf * 2 * WTILE);
        __nv_bfloat16* Wl = (__nv_bfloat16*)(sm + OFF_W + buf * 2 * WTILE + WTILE);
#pragma unroll
        for (int i = 0; i < 8; i++) {
            int idx = t + i * 256;
            int c = idx >> 4, q = idx & 15;
            int base = c * SSTR + q * 4;
            const float v[4] = {ps[i].x, ps[i].y, ps[i].z, ps[i].w};
            __nv_bfloat16 h[4], l[4];
#pragma unroll
            for (int j = 0; j < 4; j++) bsplit(v[j], h[j], l[j]);
            *(uint2*)&Sh[base] = make_uint2(packbf(h[0], h[1]), packbf(h[2], h[3]));
            *(uint2*)&Sl[base] = make_uint2(packbf(l[0], l[1]), packbf(l[2], l[3]));
        }
        // A_stack d-major: row = d (0..63), col = j.  Contiguous per-thread STS.
#pragma unroll
        for (int i = 0; i < 13; i++) {
            int idx = t + i * 256;
            if (idx < 3136) {
                int dd = idx / KHW;
                int hw = idx - dd * KHW;
                __nv_bfloat16 h, l;
                bsplit(pw0[i], h, l);
                Wh[dd * JSTR + hw] = h;        Wl[dd * JSTR + hw] = l;
                bsplit(pw1[i], h, l);
                Wh[dd * JSTR + 64 + hw] = h;   Wl[dd * JSTR + 64 + hw] = l;
            }
        }
    };

    loadchunk(0);
    storechunk(0);
    loadchunk(1);
    __syncthreads();

    // per-thread LDSM offsets (bytes)
    const unsigned offS = (unsigned)(((wr * 64 + lr + lg1 * 8) * SSTR + lg2 * 8) * 2);
    // B (trans): row = kb + lr + lg2*8 (d), col = jr + lg1*8 (j)
    const unsigned offW = (unsigned)(((lr + lg2 * 8) * JSTR + ws * 32 + lg1 * 8) * 2);

    for (int ch = 0; ch < 8; ch++) {
        if (ch + 1 < 8) storechunk((ch + 1) & 1);
        if (ch + 2 < 8) loadchunk(ch + 2);

        const unsigned aSh = smaddr(sm + (ch & 1) * 2 * STILE) + offS;
        const unsigned aSl = aSh + STILE;
        const unsigned aWh = smaddr(sm + OFF_W + (ch & 1) * 2 * WTILE) + offW;
        const unsigned aWl = aWh + WTILE;

#pragma unroll
        for (int ks = 0; ks < 4; ks++) {
            const int kb = ks * 16;
            unsigned bh[4][2], bl[4][2], r[4];
#pragma unroll
            for (int p = 0; p < 2; p++) {
                unsigned o = (unsigned)((kb * JSTR + p * 16) * 2);
                ldsm4t(r, aWh + o);
                bh[2*p][0] = r[0]; bh[2*p+1][0] = r[1]; bh[2*p][1] = r[2]; bh[2*p+1][1] = r[3];
                ldsm4t(r, aWl + o);
                bl[2*p][0] = r[0]; bl[2*p+1][0] = r[1]; bl[2*p][1] = r[2]; bl[2*p+1][1] = r[3];
            }
#pragma unroll
            for (int mi = 0; mi < 4; mi++) {
                unsigned ah[4], al[4];
                unsigned o = (unsigned)((mi * 16 * SSTR + kb) * 2);
                ldsm4(ah, aSh + o);
                ldsm4(al, aSl + o);
#pragma unroll
                for (int ni = 0; ni < 4; ni++) {
                    mma16816(acc[mi][ni], ah, bh[ni]);
                    mma16816(acc[mi][ni], ah, bl[ni]);
                    mma16816(acc[mi][ni], al, bh[ni]);
                }
            }
        }
        __syncthreads();
    }

    // stage Af[c][hw] = w0, Af[c][49+hw] = w1 (fp32) for the fold
    float* Af = (float*)sm;
    for (int idx = t; idx < 6272; idx += 256) {
        int c  = idx / KHW;
        int hw = idx - c * KHW;
        Af[c * AFSTR + hw]       = w0[c0 * KHW + idx];
        Af[c * AFSTR + KHW + hw] = w1[c0 * KHW + idx];
    }
    __syncthreads();

    float p00 = 0.f, p01 = 0.f, p10 = 0.f, p11 = 0.f;
#pragma unroll
    for (int mi = 0; mi < 4; mi++)
#pragma unroll
        for (int ni = 0; ni < 4; ni++)
#pragma unroll
            for (int v = 0; v < 4; v++) {
                int c = wr * 64 + mi * 16 + g + ((v >= 2) ? 8 : 0);
                int j = ws * 32 + ni * 8 + tg * 2 + (v & 1);
                float bv = acc[mi][ni][v];
                if (j < KHW) {
                    p00 += Af[c * AFSTR + j] * bv;
                    p01 += Af[c * AFSTR + KHW + j] * bv;
                } else if (j >= 64 && j < 64 + KHW) {
                    int hw = j - 64;
                    p10 += Af[c * AFSTR + hw] * bv;
                    p11 += Af[c * AFSTR + KHW + hw] * bv;
                }
            }

    __syncthreads();
    float* red = (float*)(sm + OFF_W);
    red[0 * 256 + t] = p00;
    red[1 * 256 + t] = p01;
    red[2 * 256 + t] = p10;
    red[3 * 256 + t] = p11;
    __syncthreads();
    for (int s = 128; s > 0; s >>= 1) {
        if (t < s) {
#pragma unroll
            for (int q = 0; q < 4; q++)
                red[q * 256 + t] += red[q * 256 + t + s];
        }
        __syncthreads();
    }
    if (t == 0) {
#pragma unroll
        for (int q = 0; q < 4; q++)
            g_spd_part[(n * 4 + blockIdx.x) * 4 + q] = red[q * 256];
    }
}

// ---------------------------------------------------------------------------
// Kernel 4: reduce SPD partials over c-tiles -> outSPD
// ---------------------------------------------------------------------------
__global__ void spd_reduce_kernel(float* __restrict__ outSPD)
{
    int i = blockIdx.x * 256 + threadIdx.x;
    if (i >= BATCH * 4) return;
    int n = i >> 2, q = i & 3;
    float s = 0.f;
#pragma unroll
    for (int dt = 0; dt < 4; dt++)
        s += g_spd_part[(n * 4 + dt) * 4 + q];
    outSPD[i] = s;
}

// ---------------------------------------------------------------------------
extern "C" void kernel_launch(void* const* d_in, const int* in_sizes, int n_in,
                              void* d_out, int out_size)
{
    const float* inputR   = (const float*)d_in[0];   // [256,512,7,7]
    const float* inputSPD = (const float*)d_in[1];   // [256,512,512]
    const float* weight   = (const float*)d_in[2];   // [1000,512,7,7]
    const float* bias     = (const float*)d_in[3];   // [1000]
    float* out = (float*)d_out;

    cudaFuncSetAttribute(gemm_mma_kernel,
                         cudaFuncAttributeMaxDynamicSharedMemorySize, GEMM_SMEM);
    cudaFuncSetAttribute(spd_mma_kernel,
                         cudaFuncAttributeMaxDynamicSharedMemorySize, SPD_SMEM);

    // 1) FC GEMM (bf16-split tensor cores, double-buffered, ldmatrix)
    gemm_mma_kernel<<<dim3(8, 2, KSPLIT), 256, GEMM_SMEM>>>(inputR, weight);

    // 2) fused reduce + bias + top-2
    reduce_top2_kernel<<<BATCH, 256>>>(bias, out);

    // 3) SPD path: B = S*A_stack per sample, fold against weights
    spd_mma_kernel<<<dim3(4, BATCH), 256, SPD_SMEM>>>(inputSPD, weight);

    // 4) reduce SPD partials
    spd_reduce_kernel<<<4, 256>>>(out + BATCH * COUT);
}